// round 1
// baseline (speedup 1.0000x reference)
#include <cuda_runtime.h>
#include <cuda_bf16.h>
#include <math.h>

// Problem constants
#define BATCH   512
#define DIM     256
#define NTREES  512
#define DEPTH   6
#define UNITS   3
#define NLEAVES 64
#define NCOLS   (NTREES * DEPTH)   // 3072 sparsemax columns

// -------- device scratch (no dynamic allocation allowed) --------
__device__ float g_xT[DIM * BATCH];            // transposed x: (DIM, BATCH)
__device__ int   g_nnz[NCOLS];                 // support size per column
__device__ int   g_selidx[NCOLS * DIM];        // compacted feature indices
__device__ float g_selw[NCOLS * DIM];          // compacted sparsemax weights

// ============================================================================
// Kernel A: blocks [0, 3072): sparsemax over DIM for column (n*6+d), compacted.
//           blocks [3072, 3200): 32x32 tiled transpose of x -> g_xT.
// 256 threads per block.
// ============================================================================
__global__ void prep_kernel(const float* __restrict__ x,
                            const float* __restrict__ fsl)
{
    const int bid = blockIdx.x;
    const int tid = threadIdx.x;

    if (bid < NCOLS) {
        __shared__ float s_sort[DIM];
        __shared__ float s_scan[DIM];
        __shared__ int   s_wcnt[8];
        __shared__ int   s_woff[8];
        __shared__ float s_tau;

        // column (n,d): fsl is (DIM, NTREES, DEPTH) row-major
        const float z = fsl[tid * NCOLS + bid];
        s_sort[tid] = z;
        __syncthreads();

        // bitonic sort, descending
        #pragma unroll 1
        for (int k = 2; k <= DIM; k <<= 1) {
            #pragma unroll 1
            for (int j = k >> 1; j > 0; j >>= 1) {
                int ixj = tid ^ j;
                if (ixj > tid) {
                    float a = s_sort[tid];
                    float b = s_sort[ixj];
                    bool desc = ((tid & k) == 0);
                    if (desc ? (a < b) : (a > b)) {
                        s_sort[tid] = b;
                        s_sort[ixj] = a;
                    }
                }
                __syncthreads();
            }
        }

        // inclusive scan (Hillis-Steele) of sorted values
        const float zs = s_sort[tid];
        s_scan[tid] = zs;
        __syncthreads();
        #pragma unroll 1
        for (int off = 1; off < DIM; off <<= 1) {
            float add = (tid >= off) ? s_scan[tid - off] : 0.0f;
            __syncthreads();
            s_scan[tid] += add;
            __syncthreads();
        }
        const float cum = s_scan[tid];

        // support count k_z
        bool support = (1.0f + (float)(tid + 1) * zs) > cum;
        unsigned sm = __ballot_sync(0xffffffffu, support);
        int lane = tid & 31, wrp = tid >> 5;
        if (lane == 0) s_wcnt[wrp] = __popc(sm);
        __syncthreads();
        if (tid == 0) {
            int kz = 0;
            #pragma unroll
            for (int w = 0; w < 8; w++) kz += s_wcnt[w];
            s_tau = (s_scan[kz - 1] - 1.0f) / (float)kz;
        }
        __syncthreads();

        // weights + deterministic ordered compaction
        const float w = z - s_tau;
        const bool nz = (w > 0.0f);
        unsigned nm = __ballot_sync(0xffffffffu, nz);
        if (lane == 0) s_wcnt[wrp] = __popc(nm);
        __syncthreads();
        if (tid == 0) {
            int acc = 0;
            #pragma unroll
            for (int i = 0; i < 8; i++) { s_woff[i] = acc; acc += s_wcnt[i]; }
            g_nnz[bid] = acc;
        }
        __syncthreads();
        if (nz) {
            int pos = s_woff[wrp] + __popc(nm & ((1u << lane) - 1u));
            g_selidx[bid * DIM + pos] = tid;
            g_selw[bid * DIM + pos]   = w;
        }
    } else {
        // transpose x (BATCH=512, DIM=256) -> g_xT (DIM, BATCH)
        __shared__ float tile[32][33];
        const int t  = bid - NCOLS;      // 0..127
        const int bt = t & 15;           // 16 tiles over BATCH
        const int it = t >> 4;           // 8 tiles over DIM
        const int tx = tid & 31;
        const int ty = tid >> 5;         // 8 rows of the tile per pass
        #pragma unroll
        for (int r = 0; r < 4; r++) {
            int row = ty + r * 8;
            tile[row][tx] = x[(bt * 32 + row) * DIM + it * 32 + tx];
        }
        __syncthreads();
        #pragma unroll
        for (int r = 0; r < 4; r++) {
            int row = ty + r * 8;
            g_xT[(it * 32 + row) * BATCH + bt * 32 + tx] = tile[tx][row];
        }
    }
}

// ============================================================================
// Kernel B: one block per tree (512 blocks), one thread per batch row (512).
// Sparse gather fv -> gates -> 64 leaf probs (factored) -> response dot.
// ============================================================================
__global__ void __launch_bounds__(BATCH)
forest_kernel(const float* __restrict__ th,    // (NTREES, DEPTH)
              const float* __restrict__ lt,    // (NTREES, DEPTH)
              const float* __restrict__ resp,  // (NTREES, UNITS, NLEAVES)
              float* __restrict__ out)         // (BATCH, NTREES, UNITS)
{
    const int n = blockIdx.x;
    const int b = threadIdx.x;

    __shared__ int   s_cnt[DEPTH];
    __shared__ float s_th[DEPTH];
    __shared__ float s_lt[DEPTH];
    __shared__ short s_idx[DEPTH][DIM];
    __shared__ float s_w[DEPTH][DIM];
    __shared__ float s_resp[UNITS * NLEAVES];

    if (b < DEPTH) {
        s_cnt[b] = g_nnz[n * DEPTH + b];
        s_th[b]  = th[n * DEPTH + b];
        s_lt[b]  = lt[n * DEPTH + b];
    }
    if (b >= 64 && b < 64 + UNITS * NLEAVES)
        s_resp[b - 64] = resp[n * UNITS * NLEAVES + (b - 64)];
    __syncthreads();

    #pragma unroll 1
    for (int d = 0; d < DEPTH; d++) {
        const int cnt = s_cnt[d];
        const int col = n * DEPTH + d;
        for (int j = b; j < cnt; j += BATCH) {
            s_idx[d][j] = (short)g_selidx[col * DIM + j];
            s_w[d][j]   = g_selw[col * DIM + j];
        }
    }
    __syncthreads();

    // gather fv, compute gates
    float g[DEPTH];
    #pragma unroll
    for (int d = 0; d < DEPTH; d++) {
        float fv = 0.0f;
        const int cnt = s_cnt[d];
        #pragma unroll 1
        for (int j = 0; j < cnt; j++) {
            fv += s_w[d][j] * g_xT[(int)s_idx[d][j] * BATCH + b];
        }
        float tlv = (fv - s_th[d]) * expf(-s_lt[d]);
        g[d] = __saturatef(0.5f * tlv + 0.5f);  // sparsemoid(tl)
    }

    // leaf prob factorization: p_c = qlo[c&7] * qhi[c>>3]
    // bit d of c set -> (1 - g[d]), clear -> g[d]
    float qlo[8], qhi[8];
    #pragma unroll
    for (int c = 0; c < 8; c++) {
        float p0 = (c & 1) ? (1.0f - g[0]) : g[0];
        float p1 = (c & 2) ? (1.0f - g[1]) : g[1];
        float p2 = (c & 4) ? (1.0f - g[2]) : g[2];
        qlo[c] = p0 * p1 * p2;
        float p3 = (c & 1) ? (1.0f - g[3]) : g[3];
        float p4 = (c & 2) ? (1.0f - g[4]) : g[4];
        float p5 = (c & 4) ? (1.0f - g[5]) : g[5];
        qhi[c] = p3 * p4 * p5;
    }

    float acc0 = 0.0f, acc1 = 0.0f, acc2 = 0.0f;
    #pragma unroll
    for (int hi = 0; hi < 8; hi++) {
        #pragma unroll
        for (int lo = 0; lo < 8; lo++) {
            int c = hi * 8 + lo;
            float p = qhi[hi] * qlo[lo];
            acc0 += p * s_resp[c];
            acc1 += p * s_resp[NLEAVES + c];
            acc2 += p * s_resp[2 * NLEAVES + c];
        }
    }

    float* o = out + ((size_t)b * NTREES + n) * UNITS;
    o[0] = acc0;
    o[1] = acc1;
    o[2] = acc2;
}

// ============================================================================
extern "C" void kernel_launch(void* const* d_in, const int* in_sizes, int n_in,
                              void* d_out, int out_size)
{
    const float* x    = (const float*)d_in[0];  // (512, 256)
    const float* fsl  = (const float*)d_in[1];  // (256, 512, 6)
    const float* th   = (const float*)d_in[2];  // (512, 6)
    const float* lt   = (const float*)d_in[3];  // (512, 6)
    const float* resp = (const float*)d_in[4];  // (512, 3, 64)
    float* out = (float*)d_out;                 // (512, 512, 3)

    prep_kernel<<<NCOLS + 128, 256>>>(x, fsl);
    forest_kernel<<<NTREES, BATCH>>>(th, lt, resp, out);
}

// round 2
// speedup vs baseline: 2.0259x; 2.0259x over previous
#include <cuda_runtime.h>
#include <cuda_bf16.h>
#include <math.h>

// Problem constants
#define BATCH   512
#define DIM     256
#define NTREES  512
#define DEPTH   6
#define UNITS   3
#define NLEAVES 64
#define NCOLS   (NTREES * DEPTH)   // 3072 sparsemax columns
#define MAXC    128                // max supported sparsemax support size per column

// -------- device scratch (no dynamic allocation allowed) --------
__device__ float g_xT[DIM * BATCH];            // transposed x: (DIM, BATCH)
__device__ int   g_nnz[NCOLS];                 // support size per column
__device__ int   g_selidx[NCOLS * DIM];        // compacted feature indices
__device__ float g_selw[NCOLS * DIM];          // compacted sparsemax weights

// ============================================================================
// Kernel A: blocks [0, 384): 8 warps/block, one warp per sparsemax column.
//           Michelot's algorithm (iterative simplex projection) — no sort,
//           no __syncthreads, only warp shuffles.
//           blocks [384, 512): 32x32 tiled transpose of x -> g_xT.
// 256 threads per block.
// ============================================================================
__global__ void __launch_bounds__(256)
prep_kernel(const float* __restrict__ x,
            const float* __restrict__ fsl)
{
    const int bid = blockIdx.x;
    const int tid = threadIdx.x;

    if (bid < NCOLS / 8) {
        const int warp = tid >> 5;
        const int lane = tid & 31;
        const int col  = bid * 8 + warp;

        // lane holds z for features i = j*32 + lane, j = 0..7
        float z[8];
        #pragma unroll
        for (int j = 0; j < 8; j++)
            z[j] = fsl[(j * 32 + lane) * NCOLS + col];

        // Michelot: S_0 = all; tau = (sum(S)-1)/|S|; S <- {z > tau}; repeat.
        float tau = -1e30f;
        int k_prev = -1;
        #pragma unroll 1
        for (int it = 0; it < 32; it++) {
            float s = 0.0f;
            int   k = 0;
            #pragma unroll
            for (int j = 0; j < 8; j++)
                if (z[j] > tau) { s += z[j]; k++; }
            #pragma unroll
            for (int o = 16; o > 0; o >>= 1) {
                s += __shfl_xor_sync(0xffffffffu, s, o);
                k += __shfl_xor_sync(0xffffffffu, k, o);
            }
            if (k == k_prev) break;      // support stable -> converged
            k_prev = k;
            tau = (s - 1.0f) / (float)k;
        }

        // compact nonzero weights (order irrelevant: fp tolerance 1e-3)
        int base = 0;
        #pragma unroll
        for (int j = 0; j < 8; j++) {
            const bool nz = (z[j] > tau);
            const unsigned m = __ballot_sync(0xffffffffu, nz);
            if (nz) {
                int pos = base + __popc(m & ((1u << lane) - 1u));
                g_selidx[col * DIM + pos] = j * 32 + lane;
                g_selw[col * DIM + pos]   = z[j] - tau;
            }
            base += __popc(m);
        }
        if (lane == 0) g_nnz[col] = base;
    } else {
        // transpose x (BATCH=512, DIM=256) -> g_xT (DIM, BATCH)
        __shared__ float tile[32][33];
        const int t  = bid - NCOLS / 8;  // 0..127
        const int bt = t & 15;           // 16 tiles over BATCH
        const int it = t >> 4;           // 8 tiles over DIM
        const int tx = tid & 31;
        const int ty = tid >> 5;
        #pragma unroll
        for (int r = 0; r < 4; r++) {
            int row = ty + r * 8;
            tile[row][tx] = x[(bt * 32 + row) * DIM + it * 32 + tx];
        }
        __syncthreads();
        #pragma unroll
        for (int r = 0; r < 4; r++) {
            int row = ty + r * 8;
            g_xT[(it * 32 + row) * BATCH + bt * 32 + tx] = tile[tx][row];
        }
    }
}

// ============================================================================
// Kernel B: 1024 blocks of 256 threads. Block = (tree n, half of batch).
// All 6 depth lists padded to common even length -> inner d-loop issues
// 12 independent global loads per 2-step j iteration (MLP 12).
// ============================================================================
__global__ void __launch_bounds__(256)
forest_kernel(const float* __restrict__ th,    // (NTREES, DEPTH)
              const float* __restrict__ lt,    // (NTREES, DEPTH)
              const float* __restrict__ resp,  // (NTREES, UNITS, NLEAVES)
              float* __restrict__ out)         // (BATCH, NTREES, UNITS)
{
    const int n   = blockIdx.x >> 1;
    const int tid = threadIdx.x;
    const int b   = (blockIdx.x & 1) * 256 + tid;

    __shared__ int    s_cnt[8];
    __shared__ float  s_th[8];
    __shared__ float  s_lt[8];
    __shared__ float2 s_list[DEPTH][MAXC];     // .x = idx*BATCH (as int bits), .y = w
    __shared__ float4 s_resp4[UNITS * NLEAVES / 4];  // 48 x float4

    if (tid < DEPTH) {
        s_cnt[tid] = g_nnz[n * DEPTH + tid];
        s_th[tid]  = th[n * DEPTH + tid];
        s_lt[tid]  = lt[n * DEPTH + tid];
    }
    if (tid >= 32 && tid < 32 + UNITS * NLEAVES / 4)
        s_resp4[tid - 32] = ((const float4*)resp)[n * (UNITS * NLEAVES / 4) + (tid - 32)];
    __syncthreads();

    // common padded length (even)
    int cm = 0;
    #pragma unroll
    for (int d = 0; d < DEPTH; d++) cm = max(cm, s_cnt[d]);
    cm = (cm + 1) & ~1;

    #pragma unroll
    for (int d = 0; d < DEPTH; d++) {
        const int cnt = s_cnt[d];
        const int col = n * DEPTH + d;
        for (int j = tid; j < cm; j += 256) {
            int   idx = 0;
            float w   = 0.0f;
            if (j < cnt) {
                idx = g_selidx[col * DIM + j] * BATCH;
                w   = g_selw[col * DIM + j];
            }
            s_list[d][j] = make_float2(__int_as_float(idx), w);
        }
    }
    __syncthreads();

    // sparse gather: fv[d] = sum_j w * xT[idx][b], 12 loads in flight
    const float* xb = g_xT + b;
    float fv[DEPTH];
    #pragma unroll
    for (int d = 0; d < DEPTH; d++) fv[d] = 0.0f;

    #pragma unroll 1
    for (int j = 0; j < cm; j += 2) {
        #pragma unroll
        for (int jj = 0; jj < 2; jj++) {
            #pragma unroll
            for (int d = 0; d < DEPTH; d++) {
                float2 e = s_list[d][j + jj];
                fv[d] += e.y * xb[__float_as_int(e.x)];
            }
        }
    }

    // gates
    float g[DEPTH];
    #pragma unroll
    for (int d = 0; d < DEPTH; d++) {
        float tlv = (fv[d] - s_th[d]) * __expf(-s_lt[d]);
        g[d] = __saturatef(0.5f * tlv + 0.5f);   // sparsemoid(tl)
    }

    // leaf prob factorization: p_c = qlo[c&7] * qhi[c>>3]
    // bit d of c set -> (1 - g[d]), clear -> g[d]
    float qlo[8], qhi[8];
    #pragma unroll
    for (int c = 0; c < 8; c++) {
        float p0 = (c & 1) ? (1.0f - g[0]) : g[0];
        float p1 = (c & 2) ? (1.0f - g[1]) : g[1];
        float p2 = (c & 4) ? (1.0f - g[2]) : g[2];
        qlo[c] = p0 * p1 * p2;
        float p3 = (c & 1) ? (1.0f - g[3]) : g[3];
        float p4 = (c & 2) ? (1.0f - g[4]) : g[4];
        float p5 = (c & 4) ? (1.0f - g[5]) : g[5];
        qhi[c] = p3 * p4 * p5;
    }

    // response contraction with float4 shared loads
    float acc0 = 0.0f, acc1 = 0.0f, acc2 = 0.0f;
    #pragma unroll
    for (int hi = 0; hi < 8; hi++) {
        const float qh = qhi[hi];
        #pragma unroll
        for (int u = 0; u < UNITS; u++) {
            float4 a = s_resp4[(u * NLEAVES + hi * 8) / 4];
            float4 c = s_resp4[(u * NLEAVES + hi * 8) / 4 + 1];
            float t = a.x * qlo[0] + a.y * qlo[1] + a.z * qlo[2] + a.w * qlo[3]
                    + c.x * qlo[4] + c.y * qlo[5] + c.z * qlo[6] + c.w * qlo[7];
            if (u == 0) acc0 += qh * t;
            else if (u == 1) acc1 += qh * t;
            else acc2 += qh * t;
        }
    }

    float* o = out + ((size_t)b * NTREES + n) * UNITS;
    o[0] = acc0;
    o[1] = acc1;
    o[2] = acc2;
}

// ============================================================================
extern "C" void kernel_launch(void* const* d_in, const int* in_sizes, int n_in,
                              void* d_out, int out_size)
{
    const float* x    = (const float*)d_in[0];  // (512, 256)
    const float* fsl  = (const float*)d_in[1];  // (256, 512, 6)
    const float* th   = (const float*)d_in[2];  // (512, 6)
    const float* lt   = (const float*)d_in[3];  // (512, 6)
    const float* resp = (const float*)d_in[4];  // (512, 3, 64)
    float* out = (float*)d_out;                 // (512, 512, 3)

    prep_kernel<<<NCOLS / 8 + 128, 256>>>(x, fsl);
    forest_kernel<<<NTREES * 2, 256>>>(th, lt, resp, out);
}

// round 3
// speedup vs baseline: 2.1941x; 1.0830x over previous
#include <cuda_runtime.h>
#include <cuda_bf16.h>
#include <math.h>

// Problem constants
#define BATCH   512
#define DIM     256
#define NTREES  512
#define DEPTH   6
#define UNITS   3
#define NLEAVES 64
#define NCOLS   (NTREES * DEPTH)   // 3072 sparsemax columns
#define MAXC    128                // max sparsemax support per column (smem tile)

// -------- device scratch (no dynamic allocation allowed) --------
__device__ float  g_xT[DIM * BATCH];          // transposed x: (DIM, BATCH)
__device__ int    g_nnz[NCOLS];               // support size per column
__device__ float2 g_sel[NCOLS * DIM];         // interleaved (idx*BATCH as int bits, weight)

// ============================================================================
// Kernel A: blocks [0, 384): 8 warps/block, one warp per sparsemax column.
//   fsl loads staged through smem so every 32B sector is fully used.
//   Michelot's algorithm (iterative simplex projection) — warp shuffles only.
// blocks [384, 512): 32x32 tiled transpose of x -> g_xT.
// ============================================================================
__global__ void __launch_bounds__(256)
prep_kernel(const float* __restrict__ x,
            const float* __restrict__ fsl)
{
    const int bid = blockIdx.x;
    const int tid = threadIdx.x;

    if (bid < NCOLS / 8) {
        __shared__ float s_z[DIM][9];   // pad 9: conflict-free column reads
        const int warp = tid >> 5;
        const int lane = tid & 31;
        const int col0 = bid * 8;

        // coalesced staging: c = tid&7 (contiguous cols), i = iter*32 + tid>>3
        {
            const int c = tid & 7;
            const int ib = tid >> 3;
            #pragma unroll
            for (int iter = 0; iter < 8; iter++) {
                const int i = iter * 32 + ib;
                s_z[i][c] = fsl[i * NCOLS + col0 + c];
            }
        }
        __syncthreads();

        const int col = col0 + warp;
        // lane holds z for features i = j*32 + lane, j = 0..7
        float z[8];
        #pragma unroll
        for (int j = 0; j < 8; j++)
            z[j] = s_z[j * 32 + lane][warp];

        // Michelot: tau <- (sum_{z>tau} z - 1)/k until support stable
        float tau = -1e30f;
        int k_prev = -1;
        #pragma unroll 1
        for (int it = 0; it < 32; it++) {
            float s = 0.0f;
            int   k = 0;
            #pragma unroll
            for (int j = 0; j < 8; j++)
                if (z[j] > tau) { s += z[j]; k++; }
            #pragma unroll
            for (int o = 16; o > 0; o >>= 1) {
                s += __shfl_xor_sync(0xffffffffu, s, o);
                k += __shfl_xor_sync(0xffffffffu, k, o);
            }
            if (k == k_prev) break;
            k_prev = k;
            tau = (s - 1.0f) / (float)k;
        }

        // compact nonzero weights, interleaved (idx*BATCH, w)
        int base = 0;
        #pragma unroll
        for (int j = 0; j < 8; j++) {
            const bool nz = (z[j] > tau);
            const unsigned m = __ballot_sync(0xffffffffu, nz);
            if (nz) {
                int pos = base + __popc(m & ((1u << lane) - 1u));
                g_sel[col * DIM + pos] =
                    make_float2(__int_as_float((j * 32 + lane) * BATCH), z[j] - tau);
            }
            base += __popc(m);
        }
        if (lane == 0) g_nnz[col] = base;
    } else {
        // transpose x (BATCH=512, DIM=256) -> g_xT (DIM, BATCH)
        __shared__ float tile[32][33];
        const int t  = bid - NCOLS / 8;  // 0..127
        const int bt = t & 15;
        const int it = t >> 4;
        const int tx = tid & 31;
        const int ty = tid >> 5;
        #pragma unroll
        for (int r = 0; r < 4; r++) {
            int row = ty + r * 8;
            tile[row][tx] = x[(bt * 32 + row) * DIM + it * 32 + tx];
        }
        __syncthreads();
        #pragma unroll
        for (int r = 0; r < 4; r++) {
            int row = ty + r * 8;
            g_xT[(it * 32 + row) * BATCH + bt * 32 + tx] = tile[tx][row];
        }
    }
}

// ============================================================================
// Kernel B: one block per tree (512 blocks), 256 threads, 2 batch rows each
// (b = tid and b+256). Doubles ILP/MLP and halves per-output response LDS.
// ============================================================================
__global__ void __launch_bounds__(256, 3)
forest_kernel(const float* __restrict__ th,    // (NTREES, DEPTH)
              const float* __restrict__ lt,    // (NTREES, DEPTH)
              const float* __restrict__ resp,  // (NTREES, UNITS, NLEAVES)
              float* __restrict__ out)         // (BATCH, NTREES, UNITS)
{
    const int n   = blockIdx.x;
    const int tid = threadIdx.x;

    __shared__ int    s_cnt[8];
    __shared__ float  s_th[8];
    __shared__ float  s_lt[8];
    __shared__ float2 s_list[DEPTH][MAXC];
    __shared__ float4 s_resp4[UNITS * NLEAVES / 4];   // 48 x float4

    if (tid < DEPTH) {
        s_cnt[tid] = g_nnz[n * DEPTH + tid];
        s_th[tid]  = th[n * DEPTH + tid];
        s_lt[tid]  = lt[n * DEPTH + tid];
    }
    if (tid >= 32 && tid < 32 + UNITS * NLEAVES / 4)
        s_resp4[tid - 32] = ((const float4*)resp)[n * (UNITS * NLEAVES / 4) + (tid - 32)];
    __syncthreads();

    // common padded length (even)
    int cm = 0;
    #pragma unroll
    for (int d = 0; d < DEPTH; d++) cm = max(cm, s_cnt[d]);
    cm = (cm + 1) & ~1;

    #pragma unroll
    for (int d = 0; d < DEPTH; d++) {
        const int cnt = s_cnt[d];
        const int col = n * DEPTH + d;
        for (int j = tid; j < cm; j += 256) {
            float2 e = make_float2(__int_as_float(0), 0.0f);
            if (j < cnt) e = g_sel[col * DIM + j];
            s_list[d][j] = e;
        }
    }
    __syncthreads();

    // sparse gather for two batch rows: fv[d][p]
    const float* xb0 = g_xT + tid;
    const float* xb1 = g_xT + tid + 256;
    float fv[DEPTH][2];
    #pragma unroll
    for (int d = 0; d < DEPTH; d++) { fv[d][0] = 0.0f; fv[d][1] = 0.0f; }

    #pragma unroll 1
    for (int j = 0; j < cm; j += 2) {
        #pragma unroll
        for (int jj = 0; jj < 2; jj++) {
            #pragma unroll
            for (int d = 0; d < DEPTH; d++) {
                float2 e = s_list[d][j + jj];
                int off = __float_as_int(e.x);
                fv[d][0] += e.y * xb0[off];
                fv[d][1] += e.y * xb1[off];
            }
        }
    }

    // gates
    float g[DEPTH][2];
    #pragma unroll
    for (int d = 0; d < DEPTH; d++) {
        float et = __expf(-s_lt[d]);
        g[d][0] = __saturatef(0.5f * ((fv[d][0] - s_th[d]) * et) + 0.5f);
        g[d][1] = __saturatef(0.5f * ((fv[d][1] - s_th[d]) * et) + 0.5f);
    }

    // leaf prob factorization: p_c = qlo[c&7] * qhi[c>>3]
    float qlo[8][2], qhi[8][2];
    #pragma unroll
    for (int c = 0; c < 8; c++) {
        #pragma unroll
        for (int p = 0; p < 2; p++) {
            float p0 = (c & 1) ? (1.0f - g[0][p]) : g[0][p];
            float p1 = (c & 2) ? (1.0f - g[1][p]) : g[1][p];
            float p2 = (c & 4) ? (1.0f - g[2][p]) : g[2][p];
            qlo[c][p] = p0 * p1 * p2;
            float p3 = (c & 1) ? (1.0f - g[3][p]) : g[3][p];
            float p4 = (c & 2) ? (1.0f - g[4][p]) : g[4][p];
            float p5 = (c & 4) ? (1.0f - g[5][p]) : g[5][p];
            qhi[c][p] = p3 * p4 * p5;
        }
    }

    // response contraction: R-tile shared across both batch rows
    float acc[UNITS][2];
    #pragma unroll
    for (int u = 0; u < UNITS; u++) { acc[u][0] = 0.0f; acc[u][1] = 0.0f; }

    #pragma unroll
    for (int hi = 0; hi < 8; hi++) {
        #pragma unroll
        for (int u = 0; u < UNITS; u++) {
            float4 a = s_resp4[(u * NLEAVES + hi * 8) / 4];
            float4 c = s_resp4[(u * NLEAVES + hi * 8) / 4 + 1];
            #pragma unroll
            for (int p = 0; p < 2; p++) {
                float t = a.x * qlo[0][p] + a.y * qlo[1][p]
                        + a.z * qlo[2][p] + a.w * qlo[3][p]
                        + c.x * qlo[4][p] + c.y * qlo[5][p]
                        + c.z * qlo[6][p] + c.w * qlo[7][p];
                acc[u][p] += qhi[hi][p] * t;
            }
        }
    }

    float* o0 = out + ((size_t)tid * NTREES + n) * UNITS;
    float* o1 = out + ((size_t)(tid + 256) * NTREES + n) * UNITS;
    o0[0] = acc[0][0]; o0[1] = acc[1][0]; o0[2] = acc[2][0];
    o1[0] = acc[0][1]; o1[1] = acc[1][1]; o1[2] = acc[2][1];
}

// ============================================================================
extern "C" void kernel_launch(void* const* d_in, const int* in_sizes, int n_in,
                              void* d_out, int out_size)
{
    const float* x    = (const float*)d_in[0];  // (512, 256)
    const float* fsl  = (const float*)d_in[1];  // (256, 512, 6)
    const float* th   = (const float*)d_in[2];  // (512, 6)
    const float* lt   = (const float*)d_in[3];  // (512, 6)
    const float* resp = (const float*)d_in[4];  // (512, 3, 64)
    float* out = (float*)d_out;                 // (512, 512, 3)

    prep_kernel<<<NCOLS / 8 + 128, 256>>>(x, fsl);
    forest_kernel<<<NTREES, 256>>>(th, lt, resp, out);
}

// round 4
// speedup vs baseline: 2.3894x; 1.0890x over previous
#include <cuda_runtime.h>
#include <cuda_bf16.h>
#include <math.h>

// Problem constants
#define BATCH   512
#define DIM     256
#define NTREES  512
#define DEPTH   6
#define UNITS   3
#define NLEAVES 64
#define NCOLS   (NTREES * DEPTH)   // 3072 sparsemax columns

// -------- device scratch (no dynamic allocation allowed) --------
__device__ float  g_xT[DIM * BATCH];      // transposed x: (DIM, BATCH)
__device__ int    g_nnz[NCOLS];           // support size per column
__device__ float2 g_sel[NCOLS * DIM];     // interleaved (idx*BATCH as int bits, weight)
__device__ float  g_fv[NCOLS * BATCH];    // fv, layout (col, b)

// ============================================================================
// Kernel A: blocks [0, 384): 8 warps/block, one warp per sparsemax column.
//   fsl staged through smem (fully-packed sectors); Michelot projection.
// blocks [384, 512): 32x32 tiled transpose of x -> g_xT.
// ============================================================================
__global__ void __launch_bounds__(256)
prep_kernel(const float* __restrict__ x,
            const float* __restrict__ fsl)
{
    const int bid = blockIdx.x;
    const int tid = threadIdx.x;

    if (bid < NCOLS / 8) {
        __shared__ float s_z[DIM][9];   // pad 9: conflict-free column reads
        const int warp = tid >> 5;
        const int lane = tid & 31;
        const int col0 = bid * 8;

        // coalesced staging: c = tid&7 (contiguous cols), i = iter*32 + tid>>3
        {
            const int c = tid & 7;
            const int ib = tid >> 3;
            #pragma unroll
            for (int iter = 0; iter < 8; iter++) {
                const int i = iter * 32 + ib;
                s_z[i][c] = fsl[i * NCOLS + col0 + c];
            }
        }
        __syncthreads();

        const int col = col0 + warp;
        float z[8];
        #pragma unroll
        for (int j = 0; j < 8; j++)
            z[j] = s_z[j * 32 + lane][warp];

        // Michelot: tau <- (sum_{z>tau} z - 1)/k until support stable
        float tau = -1e30f;
        int k_prev = -1;
        #pragma unroll 1
        for (int it = 0; it < 32; it++) {
            float s = 0.0f;
            int   k = 0;
            #pragma unroll
            for (int j = 0; j < 8; j++)
                if (z[j] > tau) { s += z[j]; k++; }
            #pragma unroll
            for (int o = 16; o > 0; o >>= 1) {
                s += __shfl_xor_sync(0xffffffffu, s, o);
                k += __shfl_xor_sync(0xffffffffu, k, o);
            }
            if (k == k_prev) break;
            k_prev = k;
            tau = (s - 1.0f) / (float)k;
        }

        // compact nonzero weights, interleaved (idx*BATCH, w)
        int base = 0;
        #pragma unroll
        for (int j = 0; j < 8; j++) {
            const bool nz = (z[j] > tau);
            const unsigned m = __ballot_sync(0xffffffffu, nz);
            if (nz) {
                int pos = base + __popc(m & ((1u << lane) - 1u));
                g_sel[col * DIM + pos] =
                    make_float2(__int_as_float((j * 32 + lane) * BATCH), z[j] - tau);
            }
            base += __popc(m);
        }
        if (lane == 0) g_nnz[col] = base;
    } else {
        // transpose x (BATCH=512, DIM=256) -> g_xT (DIM, BATCH)
        __shared__ float tile[32][33];
        const int t  = bid - NCOLS / 8;
        const int bt = t & 15;
        const int it = t >> 4;
        const int tx = tid & 31;
        const int ty = tid >> 5;
        #pragma unroll
        for (int r = 0; r < 4; r++) {
            int row = ty + r * 8;
            tile[row][tx] = x[(bt * 32 + row) * DIM + it * 32 + tx];
        }
        __syncthreads();
        #pragma unroll
        for (int r = 0; r < 4; r++) {
            int row = ty + r * 8;
            g_xT[(it * 32 + row) * BATCH + bt * 32 + tx] = tile[tx][row];
        }
    }
}

// ============================================================================
// Kernel B: fv[col][b] = sum_j w_j * xT[idx_j][b].
// One block per column (3072 blocks, 256 threads, 2 b's per thread).
// List entries are block-uniform (L1 broadcast); all xT/fv traffic coalesced.
// ============================================================================
__global__ void __launch_bounds__(256)
fv_kernel()
{
    const int col = blockIdx.x;
    const int tid = threadIdx.x;
    const int cnt = g_nnz[col];
    const float2* __restrict__ lst = g_sel + col * DIM;

    float f0 = 0.0f, f1 = 0.0f;
    int j = 0;
    #pragma unroll 1
    for (; j + 2 <= cnt; j += 2) {
        float2 e0 = __ldg(lst + j);
        float2 e1 = __ldg(lst + j + 1);
        int o0 = __float_as_int(e0.x);
        int o1 = __float_as_int(e1.x);
        float a0 = g_xT[o0 + tid];
        float a1 = g_xT[o0 + tid + 256];
        float b0 = g_xT[o1 + tid];
        float b1 = g_xT[o1 + tid + 256];
        f0 += e0.y * a0 + e1.y * b0;
        f1 += e0.y * a1 + e1.y * b1;
    }
    if (j < cnt) {
        float2 e = __ldg(lst + j);
        int o = __float_as_int(e.x);
        f0 += e.y * g_xT[o + tid];
        f1 += e.y * g_xT[o + tid + 256];
    }
    g_fv[col * BATCH + tid]       = f0;
    g_fv[col * BATCH + tid + 256] = f1;
}

// ============================================================================
// Kernel C: lean forest. 2048 blocks x 128 threads; block = (tree n, b-tile).
// 6 coalesced fv loads -> gates -> factored leaf probs -> response dot.
// ============================================================================
__global__ void __launch_bounds__(128, 10)
forest_kernel(const float* __restrict__ th,    // (NTREES, DEPTH)
              const float* __restrict__ lt,    // (NTREES, DEPTH)
              const float* __restrict__ resp,  // (NTREES, UNITS, NLEAVES)
              float* __restrict__ out)         // (BATCH, NTREES, UNITS)
{
    const int n   = blockIdx.x >> 2;
    const int bq  = blockIdx.x & 3;
    const int tid = threadIdx.x;
    const int b   = bq * 128 + tid;

    __shared__ float4 s_resp4[UNITS * NLEAVES / 4];   // 48 x float4
    __shared__ float  s_th[DEPTH];
    __shared__ float  s_et[DEPTH];

    if (tid < UNITS * NLEAVES / 4)
        s_resp4[tid] = ((const float4*)resp)[n * (UNITS * NLEAVES / 4) + tid];
    if (tid >= 64 && tid < 64 + DEPTH) {
        s_th[tid - 64] = th[n * DEPTH + (tid - 64)];
        s_et[tid - 64] = __expf(-lt[n * DEPTH + (tid - 64)]);
    }
    __syncthreads();

    // gates from precomputed fv
    float g[DEPTH];
    #pragma unroll
    for (int d = 0; d < DEPTH; d++) {
        float fv = g_fv[(n * DEPTH + d) * BATCH + b];
        g[d] = __saturatef(0.5f * ((fv - s_th[d]) * s_et[d]) + 0.5f);
    }

    // leaf prob factorization: p_c = qlo[c&7] * qhi[c>>3]
    float qlo[8], qhi[8];
    #pragma unroll
    for (int c = 0; c < 8; c++) {
        float p0 = (c & 1) ? (1.0f - g[0]) : g[0];
        float p1 = (c & 2) ? (1.0f - g[1]) : g[1];
        float p2 = (c & 4) ? (1.0f - g[2]) : g[2];
        qlo[c] = p0 * p1 * p2;
        float p3 = (c & 1) ? (1.0f - g[3]) : g[3];
        float p4 = (c & 2) ? (1.0f - g[4]) : g[4];
        float p5 = (c & 4) ? (1.0f - g[5]) : g[5];
        qhi[c] = p3 * p4 * p5;
    }

    // response contraction
    float acc0 = 0.0f, acc1 = 0.0f, acc2 = 0.0f;
    #pragma unroll
    for (int hi = 0; hi < 8; hi++) {
        const float qh = qhi[hi];
        #pragma unroll
        for (int u = 0; u < UNITS; u++) {
            float4 a = s_resp4[(u * NLEAVES + hi * 8) / 4];
            float4 c = s_resp4[(u * NLEAVES + hi * 8) / 4 + 1];
            float t = a.x * qlo[0] + a.y * qlo[1] + a.z * qlo[2] + a.w * qlo[3]
                    + c.x * qlo[4] + c.y * qlo[5] + c.z * qlo[6] + c.w * qlo[7];
            if (u == 0) acc0 += qh * t;
            else if (u == 1) acc1 += qh * t;
            else acc2 += qh * t;
        }
    }

    float* o = out + ((size_t)b * NTREES + n) * UNITS;
    o[0] = acc0;
    o[1] = acc1;
    o[2] = acc2;
}

// ============================================================================
extern "C" void kernel_launch(void* const* d_in, const int* in_sizes, int n_in,
                              void* d_out, int out_size)
{
    const float* x    = (const float*)d_in[0];  // (512, 256)
    const float* fsl  = (const float*)d_in[1];  // (256, 512, 6)
    const float* th   = (const float*)d_in[2];  // (512, 6)
    const float* lt   = (const float*)d_in[3];  // (512, 6)
    const float* resp = (const float*)d_in[4];  // (512, 3, 64)
    float* out = (float*)d_out;                 // (512, 512, 3)

    prep_kernel<<<NCOLS / 8 + 128, 256>>>(x, fsl);
    fv_kernel<<<NCOLS, 256>>>();
    forest_kernel<<<NTREES * 4, 128>>>(th, lt, resp, out);
}